// round 4
// baseline (speedup 1.0000x reference)
#include <cuda_runtime.h>
#include <cstdint>
#include <cstddef>

// CTRNN persistent kernel, round 4: 4-way k-split, 1024 threads/CTA.
// (Round-3 architecture with the register-tail double-count bug removed:
//  the REG_U64/2 pair loop already covers all 14 u64 / 28 rows.)
// T=512, B=256, I=64, H=256. 128 CTAs x 1024 threads, 2 batches/CTA.
// Augmented K = 320 (64 input + 256 recurrent). Group g (256 threads) owns
// aug rows [80g, 80g+80): 52 rows via smem (13 chunks of 4, [chunk][j] 16B
// slots, conflict-free LDS.128) + 28 rows register-resident (14 packed u64).
// 4 partials per (batch, j) exchanged via smem; group 0 finalizes batch A,
// group 1 batch B (own partial kept in register). 2 syncthreads/step.

#define T_STEPS 512
#define BATCH   256
#define IN_SZ   64
#define HID     256
#define KAUG    320
#define NTHR    1024
#define NCTA    (BATCH / 2)

#define NGROUP        4
#define ROWS_PER_G    80
#define CHUNKS_PER_G  13          // 52 smem rows per group
#define SMEM_ROWS_G   52
#define REG_U64       14          // 28 reg rows per group
#define TOTAL_CHUNKS  (NGROUP * CHUNKS_PER_G)   // 52

typedef unsigned long long u64;

#define SMEM_W_BYTES  (TOTAL_CHUNKS * HID * 16)        // 52*256*16 = 212992
#define BUF_FLOATS    336                              // 320 + 16 pad
#define HBUF_OFF      SMEM_W_BYTES
#define RED_OFF       (HBUF_OFF + 2 * 2 * BUF_FLOATS * 4)   // + 10752
#define SMEM_TOTAL    (RED_OFF + NGROUP * 2 * HID * 4)      // + 8192 = 231936

__device__ __forceinline__ u64 fma2(u64 a, u64 b, u64 c) {
    u64 d;
    asm("fma.rn.f32x2 %0, %1, %2, %3;" : "=l"(d) : "l"(a), "l"(b), "l"(c));
    return d;
}
__device__ __forceinline__ u64 add2(u64 a, u64 b) {
    u64 d;
    asm("add.rn.f32x2 %0, %1, %2;" : "=l"(d) : "l"(a), "l"(b));
    return d;
}
__device__ __forceinline__ float sum2(u64 a) {
    float lo, hi;
    asm("mov.b64 {%0, %1}, %2;" : "=f"(lo), "=f"(hi) : "l"(a));
    return lo + hi;
}

__global__ void __launch_bounds__(NTHR, 1)
ctrnn_k4_kernel(const float* __restrict__ x,
                const float* __restrict__ h0,
                const float* __restrict__ noise,
                const float* __restrict__ Win,
                const float* __restrict__ bin,
                const float* __restrict__ Whh,
                const float* __restrict__ bhh,
                float* __restrict__ out,
                float* __restrict__ hlast)
{
    extern __shared__ unsigned char smem_raw[];
    ulonglong2* Wsm = reinterpret_cast<ulonglong2*>(smem_raw);
    float* hbuf = reinterpret_cast<float*>(smem_raw + HBUF_OFF);  // [2][2][336]
    float* red  = reinterpret_cast<float*>(smem_raw + RED_OFF);   // [4][2][256]

    const int tid = threadIdx.x;
    const int g   = tid >> 8;          // warp-group 0..3
    const int j   = tid & 255;         // output unit
    const int b0  = blockIdx.x * 2;
    const int b1  = b0 + 1;

    // ---- stage W into smem: group chunk i covers aug rows 80g+4i .. +3 ----
    for (int i = 0; i < CHUNKS_PER_G; ++i) {
        const int aug = ROWS_PER_G * g + 4 * i;
        float4 v;
        if (aug < IN_SZ) v = *reinterpret_cast<const float4*>(&Win[j * IN_SZ + aug]);
        else             v = *reinterpret_cast<const float4*>(&Whh[j * HID + (aug - IN_SZ)]);
        *reinterpret_cast<float4*>(&Wsm[(g * CHUNKS_PER_G + i) * HID + j]) = v;
    }

    // ---- register W rows: aug 80g+52 .. 80g+79 (28 floats = 14 u64) ----
    u64 wreg[REG_U64];
    const int rb = ROWS_PER_G * g + SMEM_ROWS_G;
    #pragma unroll
    for (int m = 0; m < REG_U64; ++m) {
        const int aug = rb + 2 * m;
        if (aug < IN_SZ) wreg[m] = *reinterpret_cast<const u64*>(&Win[j * IN_SZ + aug]);
        else             wreg[m] = *reinterpret_cast<const u64*>(&Whh[j * HID + (aug - IN_SZ)]);
    }

    const float bsum = bin[j] + bhh[j];

    // ---- initial staging: buffer 0 = (x_0 | h_0) for both batches ----
    float* bufA0 = hbuf;                  // [0][A]
    float* bufB0 = hbuf + BUF_FLOATS;     // [0][B]
    if (g == 0) {
        bufA0[IN_SZ + j] = h0[b0 * HID + j];
        if (j < IN_SZ) bufA0[j] = x[(size_t)b0 * IN_SZ + j];
    } else if (g == 1) {
        bufB0[IN_SZ + j] = h0[b1 * HID + j];
        if (j < IN_SZ) bufB0[j] = x[(size_t)b1 * IN_SZ + j];
    }
    float nb = noise[j] + bsum;           // only groups 0/1 keep this live
    __syncthreads();

    const int aug0 = ROWS_PER_G * g;
    const ulonglong2* wp = Wsm + (size_t)(g * CHUNKS_PER_G) * HID + j;

    for (int t = 0; t < T_STEPS; ++t) {
        const float* bufA = hbuf + ((t & 1) ? 2 * BUF_FLOATS : 0);
        const float* bufB = bufA + BUF_FLOATS;
        float* bufAn = hbuf + ((t & 1) ? 0 : 2 * BUF_FLOATS);
        float* bufBn = bufAn + BUF_FLOATS;

        // prefetch next x / noise (finalizer groups only)
        const int tn = (t + 1 < T_STEPS) ? t + 1 : t;
        float xn = 0.f, nb_next = 0.f;
        if (g < 2) {
            const int myb = (g == 0) ? b0 : b1;
            if (j < IN_SZ) xn = x[((size_t)tn * BATCH + myb) * IN_SZ + j];
            nb_next = noise[(size_t)tn * HID + j] + bsum;
        }

        const float* hAc = bufA + aug0;
        const float* hBc = bufB + aug0;

        u64 aA0 = 0, aA1 = 0, aB0 = 0, aB1 = 0;
        #pragma unroll
        for (int c = 0; c < CHUNKS_PER_G; ++c) {
            ulonglong2 w  = wp[(size_t)c * HID];
            ulonglong2 ha = *reinterpret_cast<const ulonglong2*>(&hAc[4 * c]);
            ulonglong2 hb = *reinterpret_cast<const ulonglong2*>(&hBc[4 * c]);
            aA0 = fma2(w.x, ha.x, aA0);  aA1 = fma2(w.y, ha.y, aA1);
            aB0 = fma2(w.x, hb.x, aB0);  aB1 = fma2(w.y, hb.y, aB1);
        }
        // register rows: 7 pairs of u64 cover all 28 floats (offsets +0..+27)
        #pragma unroll
        for (int i = 0; i < REG_U64 / 2; ++i) {
            ulonglong2 ha = *reinterpret_cast<const ulonglong2*>(&hAc[SMEM_ROWS_G + 4 * i]);
            ulonglong2 hb = *reinterpret_cast<const ulonglong2*>(&hBc[SMEM_ROWS_G + 4 * i]);
            aA0 = fma2(wreg[2 * i], ha.x, aA0);  aA1 = fma2(wreg[2 * i + 1], ha.y, aA1);
            aB0 = fma2(wreg[2 * i], hb.x, aB0);  aB1 = fma2(wreg[2 * i + 1], hb.y, aB1);
        }

        const float pA = sum2(add2(aA0, aA1));
        const float pB = sum2(add2(aB0, aB1));

        red[(g * 2 + 0) * HID + j] = pA;
        red[(g * 2 + 1) * HID + j] = pB;
        __syncthreads();

        if (g == 0) {
            const float pre = pA + red[2 * HID + j] + red[4 * HID + j]
                                 + red[6 * HID + j] + nb;
            const float hold = bufA[IN_SZ + j];
            const float hn   = fmaxf(hold * 0.8f + pre * 0.2f, 0.f);
            if (out) out[((size_t)t * BATCH + b0) * HID + j] = hn;
            bufAn[IN_SZ + j] = hn;
            if (j < IN_SZ) bufAn[j] = xn;
            nb = nb_next;
        } else if (g == 1) {
            const float pre = pB + red[1 * HID + j] + red[5 * HID + j]
                                 + red[7 * HID + j] + nb;
            const float hold = bufB[IN_SZ + j];
            const float hn   = fmaxf(hold * 0.8f + pre * 0.2f, 0.f);
            if (out) out[((size_t)t * BATCH + b1) * HID + j] = hn;
            bufBn[IN_SZ + j] = hn;
            if (j < IN_SZ) bufBn[j] = xn;
            nb = nb_next;
        }
        __syncthreads();
    }

    if (hlast) {
        // T_STEPS even -> final h sits in buffer 0
        if (g == 0)      hlast[b0 * HID + j] = hbuf[IN_SZ + j];
        else if (g == 1) hlast[b1 * HID + j] = hbuf[BUF_FLOATS + IN_SZ + j];
    }
}

extern "C" void kernel_launch(void* const* d_in, const int* in_sizes, int n_in,
                              void* d_out, int out_size)
{
    const float* x     = (const float*)d_in[0];   // [512,256,64]
    const float* h0    = (const float*)d_in[1];   // [256,256]
    const float* noise = (const float*)d_in[2];   // [512,256]
    const float* Win   = (const float*)d_in[3];   // [256,64]
    const float* bin   = (const float*)d_in[4];   // [256]
    const float* Whh   = (const float*)d_in[5];   // [256,256]
    const float* bhh   = (const float*)d_in[6];   // [256]

    const size_t TBH = (size_t)T_STEPS * BATCH * HID;
    const size_t BH  = (size_t)BATCH * HID;

    float* out   = nullptr;
    float* hlast = nullptr;
    if ((size_t)out_size >= TBH) {
        out = (float*)d_out;
        if ((size_t)out_size >= TBH + BH) hlast = (float*)d_out + TBH;
    } else {
        hlast = (float*)d_out;
    }

    static bool attr_set = false;
    if (!attr_set) {
        cudaFuncSetAttribute(ctrnn_k4_kernel,
                             cudaFuncAttributeMaxDynamicSharedMemorySize, SMEM_TOTAL);
        attr_set = true;
    }

    ctrnn_k4_kernel<<<NCTA, NTHR, SMEM_TOTAL>>>(
        x, h0, noise, Win, bin, Whh, bhh, out, hlast);
}

// round 5
// speedup vs baseline: 1.5353x; 1.5353x over previous
#include <cuda_runtime.h>
#include <cstdint>
#include <cstddef>

// CTRNN persistent kernel, round 5: 2 outputs per thread, 4-way k-split,
// 512 threads/CTA (R2 chassis: 128 regs/thread, 16 warps, occ 25%).
// T=512, B=256, I=64, H=256. 128 CTAs, 2 batches/CTA.
//
// Thread tid: group g = tid>>7 owns aug rows [80g, 80g+80); serves outputs
// j0 = tid&127 and j1 = j0+128. One h-broadcast LDS feeds FMAs for BOTH j
// (halves h wavefronts vs 1-j-per-thread). Per group: 48 rows from smem
// (12 chunks of 4 rows, [chunk][j] 16B slots, conflict-free LDS.128) +
// 32 rows register-resident (16 packed u64 per j).
// 4 partials per (batch, j) exchanged via smem; group 0 finalizes batch A,
// group 1 batch B. Double-buffered (x_t | h_t) state, 2 syncthreads/step.

#define T_STEPS 512
#define BATCH   256
#define IN_SZ   64
#define HID     256
#define NTHR    512
#define NCTA    (BATCH / 2)

#define NGROUP        4
#define ROWS_PER_G    80
#define CHUNKS_PER_G  12          // 48 smem rows per group
#define SMEM_ROWS_G   48
#define RF_U64        16          // 32 reg rows per group (per j)
#define TOTAL_CHUNKS  (NGROUP * CHUNKS_PER_G)   // 48

typedef unsigned long long u64;

#define SMEM_W_BYTES  (TOTAL_CHUNKS * HID * 16)        // 48*256*16 = 196608
#define BUF_FLOATS    336                              // 320 + 16 pad (16B mult)
#define HBUF_OFF      SMEM_W_BYTES
#define RED_OFF       (HBUF_OFF + 2 * 2 * BUF_FLOATS * 4)   // +10752
#define SMEM_TOTAL    (RED_OFF + 2 * NGROUP * HID * 4)      // +8192 = 215552

__device__ __forceinline__ u64 fma2(u64 a, u64 b, u64 c) {
    u64 d;
    asm("fma.rn.f32x2 %0, %1, %2, %3;" : "=l"(d) : "l"(a), "l"(b), "l"(c));
    return d;
}
__device__ __forceinline__ u64 add2(u64 a, u64 b) {
    u64 d;
    asm("add.rn.f32x2 %0, %1, %2;" : "=l"(d) : "l"(a), "l"(b));
    return d;
}
__device__ __forceinline__ float sum2(u64 a) {
    float lo, hi;
    asm("mov.b64 {%0, %1}, %2;" : "=f"(lo), "=f"(hi) : "l"(a));
    return lo + hi;
}

__device__ __forceinline__ const float* wrow(const float* Win, const float* Whh,
                                             int j, int aug) {
    // augmented row aug for output j (aug < 64 -> Win, else Whh). No 16B/8B
    // load ever straddles the 63/64 boundary (chunk bases and u64 bases even).
    return (aug < IN_SZ) ? &Win[j * IN_SZ + aug] : &Whh[j * HID + (aug - IN_SZ)];
}

__global__ void __launch_bounds__(NTHR, 1)
ctrnn_j2k4_kernel(const float* __restrict__ x,
                  const float* __restrict__ h0,
                  const float* __restrict__ noise,
                  const float* __restrict__ Win,
                  const float* __restrict__ bin,
                  const float* __restrict__ Whh,
                  const float* __restrict__ bhh,
                  float* __restrict__ out,
                  float* __restrict__ hlast)
{
    extern __shared__ unsigned char smem_raw[];
    ulonglong2* Wsm = reinterpret_cast<ulonglong2*>(smem_raw);
    float* hbuf = reinterpret_cast<float*>(smem_raw + HBUF_OFF);  // [2][2][336]
    float* red  = reinterpret_cast<float*>(smem_raw + RED_OFF);   // [2][4][256]

    const int tid = threadIdx.x;
    const int g   = tid >> 7;          // k-group 0..3
    const int jl  = tid & 127;
    const int j0  = jl;
    const int j1  = jl + 128;
    const int b0  = blockIdx.x * 2;
    const int b1  = b0 + 1;

    // ---- stage W smem: chunk i covers aug rows 80g+4i..+3, for j0 and j1 ----
    for (int i = 0; i < CHUNKS_PER_G; ++i) {
        const int aug = ROWS_PER_G * g + 4 * i;
        *reinterpret_cast<float4*>(&Wsm[(g * CHUNKS_PER_G + i) * HID + j0]) =
            *reinterpret_cast<const float4*>(wrow(Win, Whh, j0, aug));
        *reinterpret_cast<float4*>(&Wsm[(g * CHUNKS_PER_G + i) * HID + j1]) =
            *reinterpret_cast<const float4*>(wrow(Win, Whh, j1, aug));
    }

    // ---- register W rows: aug 80g+48 .. 80g+79 (32 rows = 16 u64 per j) ----
    u64 wr0[RF_U64], wr1[RF_U64];
    #pragma unroll
    for (int m = 0; m < RF_U64; ++m) {
        const int aug = ROWS_PER_G * g + SMEM_ROWS_G + 2 * m;
        wr0[m] = *reinterpret_cast<const u64*>(wrow(Win, Whh, j0, aug));
        wr1[m] = *reinterpret_cast<const u64*>(wrow(Win, Whh, j1, aug));
    }

    const float bsum0 = bin[j0] + bhh[j0];
    const float bsum1 = bin[j1] + bhh[j1];

    // ---- initial staging: buffer 0 = (x_0 | h_0) for both batches ----
    float* bufA0 = hbuf;                  // [0][A]
    float* bufB0 = hbuf + BUF_FLOATS;     // [0][B]
    if (g == 0) {
        bufA0[IN_SZ + j0] = h0[b0 * HID + j0];
        bufA0[IN_SZ + j1] = h0[b0 * HID + j1];
        if (jl < IN_SZ) bufA0[jl] = x[(size_t)b0 * IN_SZ + jl];
    } else if (g == 1) {
        bufB0[IN_SZ + j0] = h0[b1 * HID + j0];
        bufB0[IN_SZ + j1] = h0[b1 * HID + j1];
        if (jl < IN_SZ) bufB0[jl] = x[(size_t)b1 * IN_SZ + jl];
    }
    float nb0 = noise[j0] + bsum0;        // live only in groups 0/1
    float nb1 = noise[j1] + bsum1;
    __syncthreads();

    const int aug0 = ROWS_PER_G * g;
    const ulonglong2* wp0 = Wsm + (size_t)(g * CHUNKS_PER_G) * HID + j0;
    const ulonglong2* wp1 = Wsm + (size_t)(g * CHUNKS_PER_G) * HID + j1;

    for (int t = 0; t < T_STEPS; ++t) {
        const float* bufA = hbuf + ((t & 1) ? 2 * BUF_FLOATS : 0);
        const float* bufB = bufA + BUF_FLOATS;
        float* bufAn = hbuf + ((t & 1) ? 0 : 2 * BUF_FLOATS);
        float* bufBn = bufAn + BUF_FLOATS;

        // prefetch next x / noise (finalizer groups only)
        const int tn = (t + 1 < T_STEPS) ? t + 1 : t;
        float xn = 0.f, nb0n = 0.f, nb1n = 0.f;
        if (g < 2) {
            const int myb = (g == 0) ? b0 : b1;
            if (jl < IN_SZ) xn = x[((size_t)tn * BATCH + myb) * IN_SZ + jl];
            nb0n = noise[(size_t)tn * HID + j0] + bsum0;
            nb1n = noise[(size_t)tn * HID + j1] + bsum1;
        }

        const float* hAc = bufA + aug0;
        const float* hBc = bufB + aug0;

        // accumulators: [j][half] per batch
        u64 aA00 = 0, aA01 = 0, aA10 = 0, aA11 = 0;
        u64 aB00 = 0, aB01 = 0, aB10 = 0, aB11 = 0;

        #pragma unroll
        for (int c = 0; c < CHUNKS_PER_G; ++c) {
            ulonglong2 w0 = wp0[(size_t)c * HID];
            ulonglong2 w1 = wp1[(size_t)c * HID];
            ulonglong2 ha = *reinterpret_cast<const ulonglong2*>(&hAc[4 * c]);
            ulonglong2 hb = *reinterpret_cast<const ulonglong2*>(&hBc[4 * c]);
            aA00 = fma2(w0.x, ha.x, aA00);  aA01 = fma2(w0.y, ha.y, aA01);
            aA10 = fma2(w1.x, ha.x, aA10);  aA11 = fma2(w1.y, ha.y, aA11);
            aB00 = fma2(w0.x, hb.x, aB00);  aB01 = fma2(w0.y, hb.y, aB01);
            aB10 = fma2(w1.x, hb.x, aB10);  aB11 = fma2(w1.y, hb.y, aB11);
        }
        // register rows: 8 iterations of 4 rows (u64 pairs), offsets +48..+79
        #pragma unroll
        for (int i = 0; i < RF_U64 / 2; ++i) {
            ulonglong2 ha = *reinterpret_cast<const ulonglong2*>(&hAc[SMEM_ROWS_G + 4 * i]);
            ulonglong2 hb = *reinterpret_cast<const ulonglong2*>(&hBc[SMEM_ROWS_G + 4 * i]);
            aA00 = fma2(wr0[2 * i], ha.x, aA00);  aA01 = fma2(wr0[2 * i + 1], ha.y, aA01);
            aA10 = fma2(wr1[2 * i], ha.x, aA10);  aA11 = fma2(wr1[2 * i + 1], ha.y, aA11);
            aB00 = fma2(wr0[2 * i], hb.x, aB00);  aB01 = fma2(wr0[2 * i + 1], hb.y, aB01);
            aB10 = fma2(wr1[2 * i], hb.x, aB10);  aB11 = fma2(wr1[2 * i + 1], hb.y, aB11);
        }

        const float pA0 = sum2(add2(aA00, aA01));   // batch A, j0
        const float pA1 = sum2(add2(aA10, aA11));   // batch A, j1
        const float pB0 = sum2(add2(aB00, aB01));
        const float pB1 = sum2(add2(aB10, aB11));

        red[(0 * NGROUP + g) * HID + j0] = pA0;
        red[(0 * NGROUP + g) * HID + j1] = pA1;
        red[(1 * NGROUP + g) * HID + j0] = pB0;
        red[(1 * NGROUP + g) * HID + j1] = pB1;
        __syncthreads();

        if (g == 0) {
            const float* rA = red;   // [0][*][*]
            const float pre0 = pA0 + rA[1 * HID + j0] + rA[2 * HID + j0]
                                   + rA[3 * HID + j0] + nb0;
            const float pre1 = pA1 + rA[1 * HID + j1] + rA[2 * HID + j1]
                                   + rA[3 * HID + j1] + nb1;
            const float hn0 = fmaxf(bufA[IN_SZ + j0] * 0.8f + pre0 * 0.2f, 0.f);
            const float hn1 = fmaxf(bufA[IN_SZ + j1] * 0.8f + pre1 * 0.2f, 0.f);
            if (out) {
                out[((size_t)t * BATCH + b0) * HID + j0] = hn0;
                out[((size_t)t * BATCH + b0) * HID + j1] = hn1;
            }
            bufAn[IN_SZ + j0] = hn0;
            bufAn[IN_SZ + j1] = hn1;
            if (jl < IN_SZ) bufAn[jl] = xn;
            nb0 = nb0n;  nb1 = nb1n;
        } else if (g == 1) {
            const float* rB = red + NGROUP * HID;   // [1][*][*]
            const float pre0 = pB0 + rB[0 * HID + j0] + rB[2 * HID + j0]
                                   + rB[3 * HID + j0] + nb0;
            const float pre1 = pB1 + rB[0 * HID + j1] + rB[2 * HID + j1]
                                   + rB[3 * HID + j1] + nb1;
            const float hn0 = fmaxf(bufB[IN_SZ + j0] * 0.8f + pre0 * 0.2f, 0.f);
            const float hn1 = fmaxf(bufB[IN_SZ + j1] * 0.8f + pre1 * 0.2f, 0.f);
            if (out) {
                out[((size_t)t * BATCH + b1) * HID + j0] = hn0;
                out[((size_t)t * BATCH + b1) * HID + j1] = hn1;
            }
            bufBn[IN_SZ + j0] = hn0;
            bufBn[IN_SZ + j1] = hn1;
            if (jl < IN_SZ) bufBn[jl] = xn;
            nb0 = nb0n;  nb1 = nb1n;
        }
        __syncthreads();
    }

    if (hlast) {
        // T_STEPS even -> final h sits in buffer 0
        if (g == 0) {
            hlast[b0 * HID + j0] = hbuf[IN_SZ + j0];
            hlast[b0 * HID + j1] = hbuf[IN_SZ + j1];
        } else if (g == 1) {
            hlast[b1 * HID + j0] = hbuf[BUF_FLOATS + IN_SZ + j0];
            hlast[b1 * HID + j1] = hbuf[BUF_FLOATS + IN_SZ + j1];
        }
    }
}

extern "C" void kernel_launch(void* const* d_in, const int* in_sizes, int n_in,
                              void* d_out, int out_size)
{
    const float* x     = (const float*)d_in[0];   // [512,256,64]
    const float* h0    = (const float*)d_in[1];   // [256,256]
    const float* noise = (const float*)d_in[2];   // [512,256]
    const float* Win   = (const float*)d_in[3];   // [256,64]
    const float* bin   = (const float*)d_in[4];   // [256]
    const float* Whh   = (const float*)d_in[5];   // [256,256]
    const float* bhh   = (const float*)d_in[6];   // [256]

    const size_t TBH = (size_t)T_STEPS * BATCH * HID;
    const size_t BH  = (size_t)BATCH * HID;

    float* out   = nullptr;
    float* hlast = nullptr;
    if ((size_t)out_size >= TBH) {
        out = (float*)d_out;
        if ((size_t)out_size >= TBH + BH) hlast = (float*)d_out + TBH;
    } else {
        hlast = (float*)d_out;
    }

    static bool attr_set = false;
    if (!attr_set) {
        cudaFuncSetAttribute(ctrnn_j2k4_kernel,
                             cudaFuncAttributeMaxDynamicSharedMemorySize, SMEM_TOTAL);
        attr_set = true;
    }

    ctrnn_j2k4_kernel<<<NCTA, NTHR, SMEM_TOTAL>>>(
        x, h0, noise, Win, bin, Whh, bhh, out, hlast);
}